// round 1
// baseline (speedup 1.0000x reference)
#include <cuda_runtime.h>
#include <math.h>

#define SQ 64
#define NB 64
#define NV 10000
#define NE 1024
#define NH 1024

// Scratch (device globals: no allocations allowed)
__device__ float g_Xp[SQ * NB * NH];   // x@W0^T + b0, per step   (16 MB)
__device__ float g_H1[SQ * NB * NH];   // h1 history for logits   (16 MB)
__device__ float g_h0[2 * NB * NH];    // ping-pong layer-0 state
__device__ float g_h1[2 * NB * NH];    // ping-pong layer-1 state

// ---------------------------------------------------------------------------
// init / finalize
// ---------------------------------------------------------------------------
__global__ void init_hidden_k(const float* __restrict__ hidden) {
    int i = blockIdx.x * blockDim.x + threadIdx.x;
    if (i < NB * NH) {
        g_h0[i] = hidden[i];
        g_h1[i] = hidden[NB * NH + i];
    }
}

__global__ void write_hidden_k(float* __restrict__ out) {
    int i = blockIdx.x * blockDim.x + threadIdx.x;
    if (i < NB * NH) {
        out[i]           = g_h0[i];   // after 64 steps, final state is in ping 0
        out[NB * NH + i] = g_h1[i];
    }
}

// ---------------------------------------------------------------------------
// Generic NT GEMM: C[m][n] = bias[n] + sum_k A[m][k] * Bm[n][k]
// Optional row gather on A (idx != nullptr -> A row = idx[m]).
// TILE 128x64x16, 256 threads, 8x4 per-thread microtile, fp32.
// ---------------------------------------------------------------------------
#define TM 128
#define TN 64
#define TK 16

__global__ void __launch_bounds__(256) gemm_nt(
    const float* __restrict__ A, const int* __restrict__ idx,
    const float* __restrict__ Bm, const float* __restrict__ bias,
    float* __restrict__ C, int M, int N, int K)
{
    __shared__ float At[TK][TM + 4];   // row stride 132 floats -> 16B aligned
    __shared__ float Bt[TK][TN + 4];   // row stride 68 floats  -> 16B aligned

    int tid = threadIdx.x;
    int tx  = tid & 15;   // n: 4 cols each
    int ty  = tid >> 4;   // m: 8 rows each
    int m0  = blockIdx.x * TM;
    int n0  = blockIdx.y * TN;

    float acc[8][4];
#pragma unroll
    for (int i = 0; i < 8; i++)
#pragma unroll
        for (int j = 0; j < 4; j++) acc[i][j] = 0.f;

    for (int k0 = 0; k0 < K; k0 += TK) {
#pragma unroll
        for (int i = 0; i < 8; i++) {          // A tile: 128x16 = 2048 elems
            int e  = tid + i * 256;
            int kk = e & 15, m = e >> 4;
            int row = idx ? idx[m0 + m] : (m0 + m);
            At[kk][m] = A[(size_t)row * K + k0 + kk];
        }
#pragma unroll
        for (int i = 0; i < 4; i++) {          // B tile: 64x16 = 1024 elems
            int e  = tid + i * 256;
            int kk = e & 15, n = e >> 4;
            int gn = n0 + n;
            Bt[kk][n] = (gn < N) ? Bm[(size_t)gn * K + k0 + kk] : 0.f;
        }
        __syncthreads();

#pragma unroll
        for (int kk = 0; kk < TK; kk++) {
            float4 b4 = *(const float4*)&Bt[kk][tx * 4];
            float4 a0 = *(const float4*)&At[kk][ty * 8];
            float4 a1 = *(const float4*)&At[kk][ty * 8 + 4];
            float av[8] = {a0.x, a0.y, a0.z, a0.w, a1.x, a1.y, a1.z, a1.w};
            float bv[4] = {b4.x, b4.y, b4.z, b4.w};
#pragma unroll
            for (int i = 0; i < 8; i++)
#pragma unroll
                for (int j = 0; j < 4; j++)
                    acc[i][j] = fmaf(av[i], bv[j], acc[i][j]);
        }
        __syncthreads();
    }

#pragma unroll
    for (int i = 0; i < 8; i++) {
        int m = m0 + ty * 8 + i;
#pragma unroll
        for (int j = 0; j < 4; j++) {
            int n = n0 + tx * 4 + j;
            if (n < N)
                C[(size_t)m * N + n] = acc[i][j] + (bias ? bias[n] : 0.f);
        }
    }
}

// ---------------------------------------------------------------------------
// Recurrence step kernels (M = 64 rows, small-M specialized).
// Grid = NH/8 = 128 blocks, 256 threads; each block: 64 rows x 8 cols.
// ---------------------------------------------------------------------------
__global__ void __launch_bounds__(256) rnn_step0_k(
    const float* __restrict__ Xp_t, const float* __restrict__ h_in,
    const float* __restrict__ Wh, float* __restrict__ h_out)
{
    __shared__ float Hs[NB][33];
    __shared__ float Ws[8][33];

    int tid = threadIdx.x;
    int tx = tid & 7;          // col in tile
    int ty = tid >> 3;         // row 0..31 (also handles row+32)
    int n0 = blockIdx.x * 8;

    float acc0 = 0.f, acc1 = 0.f;

    for (int k0 = 0; k0 < NH; k0 += 32) {
#pragma unroll
        for (int i = 0; i < 8; i++) {          // 64x32 = 2048 elems
            int e = tid + i * 256;
            int b = e >> 5, k = e & 31;
            Hs[b][k] = h_in[b * NH + k0 + k];
        }
        {
            int n = tid >> 5, k = tid & 31;    // 8x32 = 256 elems
            Ws[n][k] = Wh[(n0 + n) * NH + k0 + k];
        }
        __syncthreads();

#pragma unroll
        for (int k = 0; k < 32; k++) {
            float w = Ws[tx][k];
            acc0 = fmaf(Hs[ty][k],      w, acc0);
            acc1 = fmaf(Hs[ty + 32][k], w, acc1);
        }
        __syncthreads();
    }

    int n = n0 + tx;
    h_out[ty * NH + n]        = tanhf(Xp_t[ty * NH + n] + acc0);
    h_out[(ty + 32) * NH + n] = tanhf(Xp_t[(ty + 32) * NH + n] + acc1);
}

__global__ void __launch_bounds__(256) rnn_step1_k(
    const float* __restrict__ h0_new, const float* __restrict__ h1_in,
    const float* __restrict__ W1, const float* __restrict__ Wh1,
    const float* __restrict__ b1,
    float* __restrict__ h_out, float* __restrict__ H1_t)
{
    __shared__ float Hs0[NB][33];
    __shared__ float Hs1[NB][33];
    __shared__ float Ws0[8][33];
    __shared__ float Ws1[8][33];

    int tid = threadIdx.x;
    int tx = tid & 7;
    int ty = tid >> 3;
    int n0 = blockIdx.x * 8;

    float acc0 = 0.f, acc1 = 0.f;

    for (int k0 = 0; k0 < NH; k0 += 32) {
#pragma unroll
        for (int i = 0; i < 8; i++) {
            int e = tid + i * 256;
            int b = e >> 5, k = e & 31;
            Hs0[b][k] = h0_new[b * NH + k0 + k];
            Hs1[b][k] = h1_in[b * NH + k0 + k];
        }
        {
            int n = tid >> 5, k = tid & 31;
            Ws0[n][k] = W1[(n0 + n) * NH + k0 + k];
            Ws1[n][k] = Wh1[(n0 + n) * NH + k0 + k];
        }
        __syncthreads();

#pragma unroll
        for (int k = 0; k < 32; k++) {
            float w0 = Ws0[tx][k];
            float w1 = Ws1[tx][k];
            acc0 = fmaf(Hs0[ty][k],      w0, acc0);
            acc0 = fmaf(Hs1[ty][k],      w1, acc0);
            acc1 = fmaf(Hs0[ty + 32][k], w0, acc1);
            acc1 = fmaf(Hs1[ty + 32][k], w1, acc1);
        }
        __syncthreads();
    }

    int n = n0 + tx;
    float bb = b1[n];
    float v0 = tanhf(bb + acc0);
    float v1 = tanhf(bb + acc1);
    h_out[ty * NH + n]        = v0;
    h_out[(ty + 32) * NH + n] = v1;
    H1_t[ty * NH + n]         = v0;
    H1_t[(ty + 32) * NH + n]  = v1;
}

// ---------------------------------------------------------------------------
extern "C" void kernel_launch(void* const* d_in, const int* in_sizes, int n_in,
                              void* d_out, int out_size)
{
    const int*   inputs = (const int*)  d_in[0];
    const float* hidden = (const float*)d_in[1];
    const float* emb    = (const float*)d_in[2];
    const float* W0     = (const float*)d_in[3];  (void)W0;
    const float* Wh0    = (const float*)d_in[4];
    const float* b0     = (const float*)d_in[5];
    const float* W1     = (const float*)d_in[6];
    const float* Wh1    = (const float*)d_in[7];
    const float* b1     = (const float*)d_in[8];
    const float* Wd     = (const float*)d_in[9];
    const float* bd     = (const float*)d_in[10];
    float* out = (float*)d_out;

    static float *pXp = nullptr, *pH1 = nullptr, *ph0 = nullptr, *ph1 = nullptr;
    if (!pXp) {
        cudaGetSymbolAddress((void**)&pXp, g_Xp);
        cudaGetSymbolAddress((void**)&pH1, g_H1);
        cudaGetSymbolAddress((void**)&ph0, g_h0);
        cudaGetSymbolAddress((void**)&ph1, g_h1);
    }

    init_hidden_k<<<(NB * NH + 255) / 256, 256>>>(hidden);

    // Xp[t*B+b][h] = b0[h] + emb[inputs[t,b]] . W0[h]   (gathered big GEMM)
    {
        dim3 g(SQ * NB / TM, NH / TN);
        gemm_nt<<<g, 256>>>((const float*)d_in[2], inputs, (const float*)d_in[3],
                            b0, pXp, SQ * NB, NH, NE);
    }
    (void)emb;

    // Sequential recurrence (only truly serial part)
    for (int t = 0; t < SQ; t++) {
        int pin = t & 1, pout = 1 - pin;
        rnn_step0_k<<<NH / 8, 256>>>(pXp + (size_t)t * NB * NH,
                                     ph0 + (size_t)pin * NB * NH, Wh0,
                                     ph0 + (size_t)pout * NB * NH);
        rnn_step1_k<<<NH / 8, 256>>>(ph0 + (size_t)pout * NB * NH,
                                     ph1 + (size_t)pin * NB * NH,
                                     W1, Wh1, b1,
                                     ph1 + (size_t)pout * NB * NH,
                                     pH1 + (size_t)t * NB * NH);
    }

    // logits[S*B, V] = H1 @ Wd^T + bd  (one big deferred GEMM, 71% of FLOPs)
    {
        dim3 g(SQ * NB / TM, (NV + TN - 1) / TN);
        gemm_nt<<<g, 256>>>(pH1, nullptr, Wd, bd, out, SQ * NB, NV, NH);
    }

    // final hidden states appended after logits
    if ((long long)out_size >= (long long)SQ * NB * NV + 2LL * NB * NH)
        write_hidden_k<<<(NB * NH + 255) / 256, 256>>>(out + (size_t)SQ * NB * NV);
}

// round 3
// speedup vs baseline: 1.2645x; 1.2645x over previous
#include <cuda_runtime.h>
#include <cuda_bf16.h>
#include <math.h>
#include <stdint.h>

#define SQ 64
#define NB 64
#define NV 10000
#define NVP 10112            // padded to 79*128
#define NE 1024
#define NH 1024
#define MROWS (SQ*NB)        // 4096
#define K3 3072              // extended K = 3*1024
#define NCH (K3/32)          // 96 k-chunks of 32

// ---------------------------------------------------------------------------
// Device scratch (no allocations allowed)
// ---------------------------------------------------------------------------
__device__ float g_Xp[MROWS * NH];                 // x@W0^T + b0 (fp32)
__device__ float g_h0[2 * NB * NH];                // layer0 ping-pong state
__device__ float g_h1[2 * NB * NH];                // layer1 ping-pong state
__device__ __nv_bfloat16 g_Xe[MROWS * K3];         // gathered emb, ext [hi|lo|hi]
__device__ __nv_bfloat16 g_W0e[NH * K3];           // W0 ext  [hi|hi|lo]
__device__ __nv_bfloat16 g_Wde[NVP * K3];          // Wd ext  [hi|hi|lo], padded rows
__device__ __nv_bfloat16 g_H1e[MROWS * K3];        // h1 history ext [hi|lo|hi]

// ---------------------------------------------------------------------------
// utility kernels
// ---------------------------------------------------------------------------
__global__ void init_hidden_k(const float* __restrict__ hidden) {
    int i = blockIdx.x * blockDim.x + threadIdx.x;
    if (i < NB * NH) { g_h0[i] = hidden[i]; g_h1[i] = hidden[NB * NH + i]; }
}

__global__ void write_hidden_k(float* __restrict__ out) {
    int i = blockIdx.x * blockDim.x + threadIdx.x;
    if (i < NB * NH) { out[i] = g_h0[i]; out[NB * NH + i] = g_h1[i]; }
}

// B-side extended split: dst[r][k]=hi, dst[r][1024+k]=hi, dst[r][2048+k]=lo
__global__ void splitB_k(const float* __restrict__ src, __nv_bfloat16* __restrict__ dst,
                         int rows, int rowsPad) {
    int i = blockIdx.x * blockDim.x + threadIdx.x;
    if (i >= rowsPad * NH) return;
    int r = i >> 10, k = i & 1023;
    float f = (r < rows) ? src[(size_t)r * NH + k] : 0.f;
    __nv_bfloat16 hi = __float2bfloat16(f);
    __nv_bfloat16 lo = __float2bfloat16(f - __bfloat162float(hi));
    __nv_bfloat16* d = dst + (size_t)r * K3 + k;
    d[0]    = hi;
    d[1024] = hi;
    d[2048] = lo;
}

// A-side gather+split: row = t*NB+b, x = emb[inputs[row]]; [hi|lo|hi]
__global__ void gather_splitA_k(const float* __restrict__ emb, const int* __restrict__ inputs,
                                __nv_bfloat16* __restrict__ dst) {
    int row = blockIdx.x;
    int tok = inputs[row];
    const float* src = emb + (size_t)tok * NE;
    __nv_bfloat16* d = dst + (size_t)row * K3;
    for (int j = threadIdx.x; j < NE; j += blockDim.x) {
        float f = src[j];
        __nv_bfloat16 hi = __float2bfloat16(f);
        __nv_bfloat16 lo = __float2bfloat16(f - __bfloat162float(hi));
        d[j]        = hi;
        d[1024 + j] = lo;
        d[2048 + j] = hi;
    }
}

// ---------------------------------------------------------------------------
// bf16 mma.sync GEMM:  C[m][n] = bias[n] + sum_k A[m][k]*B[n][k]
// A: [4096, K3] row-major, B: [rowsPad, K3] row-major (rowsPad % 128 == 0).
// CTA tile 128x128, 8 warps (warp tile 32x64), K-chunk 32, 2-stage cp.async.
// grid = (32, rowsPad/128), 256 threads.
// ---------------------------------------------------------------------------
__device__ __forceinline__ uint32_t smem_u32(const void* p) {
    uint32_t a;
    asm("{ .reg .u64 t; cvta.to.shared.u64 t, %1; cvt.u32.u64 %0, t; }" : "=r"(a) : "l"(p));
    return a;
}
__device__ __forceinline__ void cpasync16(uint32_t dst, const void* src) {
    asm volatile("cp.async.cg.shared.global [%0], [%1], 16;" :: "r"(dst), "l"(src) : "memory");
}
__device__ __forceinline__ void ldmat4(uint32_t* r, uint32_t addr) {
    asm volatile("ldmatrix.sync.aligned.m8n8.x4.shared.b16 {%0,%1,%2,%3}, [%4];"
                 : "=r"(r[0]), "=r"(r[1]), "=r"(r[2]), "=r"(r[3]) : "r"(addr));
}
__device__ __forceinline__ void mma16816(float* c, const uint32_t* a, const uint32_t* b) {
    asm volatile("mma.sync.aligned.m16n8k16.row.col.f32.bf16.bf16.f32 "
                 "{%0,%1,%2,%3}, {%4,%5,%6,%7}, {%8,%9}, {%0,%1,%2,%3};"
                 : "+f"(c[0]), "+f"(c[1]), "+f"(c[2]), "+f"(c[3])
                 : "r"(a[0]), "r"(a[1]), "r"(a[2]), "r"(a[3]), "r"(b[0]), "r"(b[1]));
}

#define SPITCH 40   // bf16 pitch per 32-wide row (80B, 16B-aligned, conflict-free phases)

__global__ void __launch_bounds__(256, 2) gemm_mma(
    const __nv_bfloat16* __restrict__ A, const __nv_bfloat16* __restrict__ B,
    const float* __restrict__ bias, float* __restrict__ C, int Ntot)
{
    __shared__ __nv_bfloat16 As[2][128][SPITCH];
    __shared__ __nv_bfloat16 Bs[2][128][SPITCH];

    int tid  = threadIdx.x;
    int lane = tid & 31;
    int wid  = tid >> 5;
    int wm   = (wid & 3) * 32;       // warp M offset
    int wn   = (wid >> 2) * 64;      // warp N offset
    int bm   = blockIdx.x * 128;
    int bn   = blockIdx.y * 128;

    uint32_t sA[2] = { smem_u32(&As[0][0][0]), smem_u32(&As[1][0][0]) };
    uint32_t sB[2] = { smem_u32(&Bs[0][0][0]), smem_u32(&Bs[1][0][0]) };

    float acc[2][8][4];
#pragma unroll
    for (int mt = 0; mt < 2; mt++)
#pragma unroll
        for (int nt = 0; nt < 8; nt++)
#pragma unroll
            for (int j = 0; j < 4; j++) acc[mt][nt][j] = 0.f;

    // per-thread load indices: 2 x 16B for A, 2 x 16B for B per chunk
    int lrow[2], lseg[2];
#pragma unroll
    for (int i = 0; i < 2; i++) {
        int u = tid + i * 256;       // 0..511
        lrow[i] = u >> 2;
        lseg[i] = u & 3;
    }

    // prologue: load chunk 0 into stage 0
#pragma unroll
    for (int i = 0; i < 2; i++) {
        const __nv_bfloat16* ga = A + (size_t)(bm + lrow[i]) * K3 + lseg[i] * 8;
        const __nv_bfloat16* gb = B + (size_t)(bn + lrow[i]) * K3 + lseg[i] * 8;
        uint32_t off = (uint32_t)(lrow[i] * SPITCH + lseg[i] * 8) * 2;
        cpasync16(sA[0] + off, ga);
        cpasync16(sB[0] + off, gb);
    }
    asm volatile("cp.async.commit_group;" ::: "memory");

    for (int c = 0; c < NCH; c++) {
        int s = c & 1;
        if (c + 1 < NCH) {
            int koff = (c + 1) * 32;
#pragma unroll
            for (int i = 0; i < 2; i++) {
                const __nv_bfloat16* ga = A + (size_t)(bm + lrow[i]) * K3 + koff + lseg[i] * 8;
                const __nv_bfloat16* gb = B + (size_t)(bn + lrow[i]) * K3 + koff + lseg[i] * 8;
                uint32_t off = (uint32_t)(lrow[i] * SPITCH + lseg[i] * 8) * 2;
                cpasync16(sA[s ^ 1] + off, ga);
                cpasync16(sB[s ^ 1] + off, gb);
            }
            asm volatile("cp.async.commit_group;" ::: "memory");
            asm volatile("cp.async.wait_group 1;" ::: "memory");
        } else {
            asm volatile("cp.async.wait_group 0;" ::: "memory");
        }
        __syncthreads();

        // compute chunk c from stage s
#pragma unroll
        for (int kk = 0; kk < 2; kk++) {
            uint32_t a[2][4], b[8][2];
#pragma unroll
            for (int mt = 0; mt < 2; mt++) {
                uint32_t addr = sA[s] +
                    (uint32_t)((wm + mt * 16 + (lane & 15)) * SPITCH + kk * 16 + (lane >> 4) * 8) * 2;
                ldmat4(a[mt], addr);
            }
#pragma unroll
            for (int np = 0; np < 4; np++) {
                int brow = wn + np * 16 + (lane & 7) + ((lane & 16) ? 8 : 0);
                int bcol = kk * 16 + ((lane & 8) ? 8 : 0);
                uint32_t addr = sB[s] + (uint32_t)(brow * SPITCH + bcol) * 2;
                uint32_t q[4];
                ldmat4(q, addr);
                b[np * 2][0]     = q[0]; b[np * 2][1]     = q[1];
                b[np * 2 + 1][0] = q[2]; b[np * 2 + 1][1] = q[3];
            }
#pragma unroll
            for (int mt = 0; mt < 2; mt++)
#pragma unroll
                for (int nt = 0; nt < 8; nt++)
                    mma16816(acc[mt][nt], a[mt], b[nt]);
        }
        __syncthreads();
    }

    // epilogue: direct global write with bias (float2 per fragment row)
#pragma unroll
    for (int mt = 0; mt < 2; mt++) {
#pragma unroll
        for (int nt = 0; nt < 8; nt++) {
            int col = wn + nt * 8 + (lane & 3) * 2;
            int gcol = bn + col;
            if (gcol >= Ntot) continue;
            float bx = bias[gcol], by = bias[gcol + 1];
            int r0 = bm + wm + mt * 16 + (lane >> 2);
            float2 v0 = make_float2(acc[mt][nt][0] + bx, acc[mt][nt][1] + by);
            float2 v1 = make_float2(acc[mt][nt][2] + bx, acc[mt][nt][3] + by);
            *(float2*)(C + (size_t)r0 * Ntot + gcol) = v0;
            *(float2*)(C + (size_t)(r0 + 8) * Ntot + gcol) = v1;
        }
    }
}

// ---------------------------------------------------------------------------
// Recurrence step kernels (fp32 SIMT)
// ---------------------------------------------------------------------------
__global__ void __launch_bounds__(256) rnn_step0_k(
    const float* __restrict__ Xp_t, const float* __restrict__ h_in,
    const float* __restrict__ Wh, float* __restrict__ h_out)
{
    __shared__ float Hs[NB][33];
    __shared__ float Ws[8][33];
    int tid = threadIdx.x;
    int tx = tid & 7, ty = tid >> 3;
    int n0 = blockIdx.x * 8;
    float acc0 = 0.f, acc1 = 0.f;

    for (int k0 = 0; k0 < NH; k0 += 32) {
#pragma unroll
        for (int i = 0; i < 8; i++) {
            int e = tid + i * 256;
            int b = e >> 5, k = e & 31;
            Hs[b][k] = h_in[b * NH + k0 + k];
        }
        { int n = tid >> 5, k = tid & 31; Ws[n][k] = Wh[(n0 + n) * NH + k0 + k]; }
        __syncthreads();
#pragma unroll
        for (int k = 0; k < 32; k++) {
            float w = Ws[tx][k];
            acc0 = fmaf(Hs[ty][k],      w, acc0);
            acc1 = fmaf(Hs[ty + 32][k], w, acc1);
        }
        __syncthreads();
    }
    int n = n0 + tx;
    h_out[ty * NH + n]        = tanhf(Xp_t[ty * NH + n] + acc0);
    h_out[(ty + 32) * NH + n] = tanhf(Xp_t[(ty + 32) * NH + n] + acc1);
}

__global__ void __launch_bounds__(256) rnn_step1_k(
    const float* __restrict__ h0_new, const float* __restrict__ h1_in,
    const float* __restrict__ W1, const float* __restrict__ Wh1,
    const float* __restrict__ b1,
    float* __restrict__ h_out, __nv_bfloat16* __restrict__ H1e_t)
{
    __shared__ float Hs0[NB][33];
    __shared__ float Hs1[NB][33];
    __shared__ float Ws0[8][33];
    __shared__ float Ws1[8][33];
    int tid = threadIdx.x;
    int tx = tid & 7, ty = tid >> 3;
    int n0 = blockIdx.x * 8;
    float acc0 = 0.f, acc1 = 0.f;

    for (int k0 = 0; k0 < NH; k0 += 32) {
#pragma unroll
        for (int i = 0; i < 8; i++) {
            int e = tid + i * 256;
            int b = e >> 5, k = e & 31;
            Hs0[b][k] = h0_new[b * NH + k0 + k];
            Hs1[b][k] = h1_in[b * NH + k0 + k];
        }
        { int n = tid >> 5, k = tid & 31;
          Ws0[n][k] = W1[(n0 + n) * NH + k0 + k];
          Ws1[n][k] = Wh1[(n0 + n) * NH + k0 + k]; }
        __syncthreads();
#pragma unroll
        for (int k = 0; k < 32; k++) {
            float w0 = Ws0[tx][k];
            float w1 = Ws1[tx][k];
            acc0 = fmaf(Hs0[ty][k],      w0, acc0);
            acc0 = fmaf(Hs1[ty][k],      w1, acc0);
            acc1 = fmaf(Hs0[ty + 32][k], w0, acc1);
            acc1 = fmaf(Hs1[ty + 32][k], w1, acc1);
        }
        __syncthreads();
    }
    int n = n0 + tx;
    float bb = b1[n];
    float v0 = tanhf(bb + acc0);
    float v1 = tanhf(bb + acc1);
    h_out[ty * NH + n]        = v0;
    h_out[(ty + 32) * NH + n] = v1;

    // extended A-side layout [hi | lo | hi]
    __nv_bfloat16 h0b = __float2bfloat16(v0);
    __nv_bfloat16 h1b = __float2bfloat16(v1);
    __nv_bfloat16 l0b = __float2bfloat16(v0 - __bfloat162float(h0b));
    __nv_bfloat16 l1b = __float2bfloat16(v1 - __bfloat162float(h1b));
    __nv_bfloat16* d0 = H1e_t + (size_t)ty * K3 + n;
    __nv_bfloat16* d1 = H1e_t + (size_t)(ty + 32) * K3 + n;
    d0[0] = h0b; d0[1024] = l0b; d0[2048] = h0b;
    d1[0] = h1b; d1[1024] = l1b; d1[2048] = h1b;
}

// ---------------------------------------------------------------------------
extern "C" void kernel_launch(void* const* d_in, const int* in_sizes, int n_in,
                              void* d_out, int out_size)
{
    const int*   inputs = (const int*)  d_in[0];
    const float* hidden = (const float*)d_in[1];
    const float* emb    = (const float*)d_in[2];
    const float* W0     = (const float*)d_in[3];
    const float* Wh0    = (const float*)d_in[4];
    const float* b0     = (const float*)d_in[5];
    const float* W1     = (const float*)d_in[6];
    const float* Wh1    = (const float*)d_in[7];
    const float* b1     = (const float*)d_in[8];
    const float* Wd     = (const float*)d_in[9];
    const float* bd     = (const float*)d_in[10];
    float* out = (float*)d_out;

    static bool inited = false;
    static float *pXp, *ph0, *ph1;
    static __nv_bfloat16 *pXe, *pW0e, *pWde, *pH1e;
    if (!inited) {
        cudaGetSymbolAddress((void**)&pXp,  g_Xp);
        cudaGetSymbolAddress((void**)&ph0,  g_h0);
        cudaGetSymbolAddress((void**)&ph1,  g_h1);
        cudaGetSymbolAddress((void**)&pXe,  g_Xe);
        cudaGetSymbolAddress((void**)&pW0e, g_W0e);
        cudaGetSymbolAddress((void**)&pWde, g_Wde);
        cudaGetSymbolAddress((void**)&pH1e, g_H1e);
        inited = true;
    }

    init_hidden_k<<<(NB * NH + 255) / 256, 256>>>(hidden);

    // extended bf16 conversions
    splitB_k<<<(NH * NH + 255) / 256, 256>>>(W0, pW0e, NH, NH);
    splitB_k<<<(NVP * NH + 255) / 256, 256>>>(Wd, pWde, NV, NVP);
    gather_splitA_k<<<MROWS, 256>>>(emb, inputs, pXe);

    // Xp = X @ W0^T + b0
    {
        dim3 g(MROWS / 128, NH / 128);
        gemm_mma<<<g, 256>>>(pXe, pW0e, b0, pXp, NH);
    }

    // sequential recurrence
    for (int t = 0; t < SQ; t++) {
        int pin = t & 1, pout = 1 - pin;
        rnn_step0_k<<<NH / 8, 256>>>(pXp + (size_t)t * NB * NH,
                                     ph0 + (size_t)pin * NB * NH, Wh0,
                                     ph0 + (size_t)pout * NB * NH);
        rnn_step1_k<<<NH / 8, 256>>>(ph0 + (size_t)pout * NB * NH,
                                     ph1 + (size_t)pin * NB * NH,
                                     W1, Wh1, b1,
                                     ph1 + (size_t)pout * NB * NH,
                                     pH1e + (size_t)t * NB * K3);
    }

    // logits = H1 @ Wd^T + bd
    {
        dim3 g(MROWS / 128, NVP / 128);
        gemm_mma<<<g, 256>>>(pH1e, pWde, bd, out, NV);
    }

    if ((long long)out_size >= (long long)SQ * NB * NV + 2LL * NB * NH)
        write_hidden_k<<<(NB * NH + 255) / 256, 256>>>(out + (size_t)SQ * NB * NV);
}

// round 5
// speedup vs baseline: 1.2842x; 1.0156x over previous
#include <cuda_runtime.h>
#include <cuda_bf16.h>
#include <math.h>
#include <stdint.h>

#define SQ 64
#define NB 64
#define NV 10000
#define NVP 10112            // padded to 79*128
#define NE 1024
#define NH 1024
#define MROWS (SQ*NB)        // 4096
#define K3 3072              // extended K = 3*1024
#define NCH 96               // 3072/32 k-chunks
#define NSTAGE 4

// ---------------------------------------------------------------------------
// Device scratch
// ---------------------------------------------------------------------------
__device__ float g_Xp[MROWS * NH];                 // x@W0^T + b0
__device__ float g_Yp[MROWS * NH];                 // h0@W1^T + b1
__device__ float g_h0[2 * NB * NH];
__device__ float g_h1[2 * NB * NH];
__device__ __nv_bfloat16 g_Xe[MROWS * K3];         // gathered emb ext [hi|lo|hi]
__device__ __nv_bfloat16 g_W0e[NH * K3];           // [hi|hi|lo]
__device__ __nv_bfloat16 g_W1e[NH * K3];           // [hi|hi|lo]
__device__ __nv_bfloat16 g_Wde[NVP * K3];          // [hi|hi|lo]
__device__ __nv_bfloat16 g_H0e[MROWS * K3];        // h0 history ext [hi|lo|hi]
__device__ __nv_bfloat16 g_H1e[MROWS * K3];        // h1 history ext [hi|lo|hi]

// ---------------------------------------------------------------------------
// utility kernels
// ---------------------------------------------------------------------------
__global__ void init_hidden_k(const float* __restrict__ hidden) {
    int i = blockIdx.x * blockDim.x + threadIdx.x;
    if (i < NB * NH) { g_h0[i] = hidden[i]; g_h1[i] = hidden[NB * NH + i]; }
}

__global__ void write_hidden_k(float* __restrict__ out) {
    int i = blockIdx.x * blockDim.x + threadIdx.x;
    if (i < NB * NH) { out[i] = g_h0[i]; out[NB * NH + i] = g_h1[i]; }
}

__global__ void splitB_k(const float* __restrict__ src, __nv_bfloat16* __restrict__ dst,
                         int rows, int rowsPad) {
    int i = blockIdx.x * blockDim.x + threadIdx.x;
    if (i >= rowsPad * NH) return;
    int r = i >> 10, k = i & 1023;
    float f = (r < rows) ? src[(size_t)r * NH + k] : 0.f;
    __nv_bfloat16 hi = __float2bfloat16(f);
    __nv_bfloat16 lo = __float2bfloat16(f - __bfloat162float(hi));
    __nv_bfloat16* d = dst + (size_t)r * K3 + k;
    d[0] = hi; d[1024] = hi; d[2048] = lo;
}

__global__ void gather_splitA_k(const float* __restrict__ emb, const int* __restrict__ inputs,
                                __nv_bfloat16* __restrict__ dst) {
    int row = blockIdx.x;
    int tok = inputs[row];
    const float* src = emb + (size_t)tok * NE;
    __nv_bfloat16* d = dst + (size_t)row * K3;
    for (int j = threadIdx.x; j < NE; j += blockDim.x) {
        float f = src[j];
        __nv_bfloat16 hi = __float2bfloat16(f);
        __nv_bfloat16 lo = __float2bfloat16(f - __bfloat162float(hi));
        d[j] = hi; d[1024 + j] = lo; d[2048 + j] = hi;
    }
}

// ---------------------------------------------------------------------------
// bf16 mma.sync GEMM, 4-stage cp.async pipeline.
// C[m][n] = bias[n] + sum_k A[m][k]*B[n][k]; A:[4096,K3], B:[rowsPad,K3].
// CTA 128x128, 8 warps (32x64 each), K-chunk 32. grid=(32, rowsPad/128), 256 thr.
// ---------------------------------------------------------------------------
__device__ __forceinline__ uint32_t smem_u32(const void* p) {
    uint32_t a;
    asm("{ .reg .u64 t; cvta.to.shared.u64 t, %1; cvt.u32.u64 %0, t; }" : "=r"(a) : "l"(p));
    return a;
}
__device__ __forceinline__ void cpasync16(uint32_t dst, const void* src) {
    asm volatile("cp.async.cg.shared.global [%0], [%1], 16;" :: "r"(dst), "l"(src) : "memory");
}
__device__ __forceinline__ void ldmat4(uint32_t* r, uint32_t addr) {
    asm volatile("ldmatrix.sync.aligned.m8n8.x4.shared.b16 {%0,%1,%2,%3}, [%4];"
                 : "=r"(r[0]), "=r"(r[1]), "=r"(r[2]), "=r"(r[3]) : "r"(addr));
}
__device__ __forceinline__ void mma16816(float* c, const uint32_t* a, const uint32_t* b) {
    asm volatile("mma.sync.aligned.m16n8k16.row.col.f32.bf16.bf16.f32 "
                 "{%0,%1,%2,%3}, {%4,%5,%6,%7}, {%8,%9}, {%0,%1,%2,%3};"
                 : "+f"(c[0]), "+f"(c[1]), "+f"(c[2]), "+f"(c[3])
                 : "r"(a[0]), "r"(a[1]), "r"(a[2]), "r"(a[3]), "r"(b[0]), "r"(b[1]));
}

#define SPITCH 40                       // bf16 per smem row (80B)
#define STAGE_ELEMS (2 * 128 * SPITCH)  // A tile + B tile, bf16 elems
#define GEMM_SMEM (NSTAGE * STAGE_ELEMS * 2)

__global__ void __launch_bounds__(256, 2) gemm_mma(
    const __nv_bfloat16* __restrict__ A, const __nv_bfloat16* __restrict__ B,
    const float* __restrict__ bias, float* __restrict__ C, int Ntot)
{
    extern __shared__ __nv_bfloat16 sm[];
    uint32_t sbase = smem_u32(sm);

    int tid  = threadIdx.x;
    int lane = tid & 31;
    int wid  = tid >> 5;
    int wm   = (wid & 3) * 32;
    int wn   = (wid >> 2) * 64;
    int bm   = blockIdx.x * 128;
    int bn   = blockIdx.y * 128;

    float acc[2][8][4];
#pragma unroll
    for (int mt = 0; mt < 2; mt++)
#pragma unroll
        for (int nt = 0; nt < 8; nt++)
#pragma unroll
            for (int j = 0; j < 4; j++) acc[mt][nt][j] = 0.f;

    int lrow[2], lseg[2];
#pragma unroll
    for (int i = 0; i < 2; i++) {
        int u = tid + i * 256;
        lrow[i] = u >> 2;
        lseg[i] = u & 3;
    }

    // prologue: chunks 0..2 into stages 0..2
#pragma unroll
    for (int p = 0; p < NSTAGE - 1; p++) {
        uint32_t st = sbase + p * (STAGE_ELEMS * 2);
        int koff = p * 32;
#pragma unroll
        for (int i = 0; i < 2; i++) {
            uint32_t off = (uint32_t)(lrow[i] * SPITCH + lseg[i] * 8) * 2;
            cpasync16(st + off,               A + (size_t)(bm + lrow[i]) * K3 + koff + lseg[i] * 8);
            cpasync16(st + 128 * SPITCH * 2 + off, B + (size_t)(bn + lrow[i]) * K3 + koff + lseg[i] * 8);
        }
        asm volatile("cp.async.commit_group;" ::: "memory");
    }

    for (int c = 0; c < NCH; c++) {
        asm volatile("cp.async.wait_group %0;" :: "n"(NSTAGE - 2) : "memory");
        __syncthreads();

        int cn = c + NSTAGE - 1;
        if (cn < NCH) {
            uint32_t st = sbase + (cn & (NSTAGE - 1)) * (STAGE_ELEMS * 2);
            int koff = cn * 32;
#pragma unroll
            for (int i = 0; i < 2; i++) {
                uint32_t off = (uint32_t)(lrow[i] * SPITCH + lseg[i] * 8) * 2;
                cpasync16(st + off,               A + (size_t)(bm + lrow[i]) * K3 + koff + lseg[i] * 8);
                cpasync16(st + 128 * SPITCH * 2 + off, B + (size_t)(bn + lrow[i]) * K3 + koff + lseg[i] * 8);
            }
        }
        asm volatile("cp.async.commit_group;" ::: "memory");

        uint32_t sA = sbase + (c & (NSTAGE - 1)) * (STAGE_ELEMS * 2);
        uint32_t sB = sA + 128 * SPITCH * 2;
#pragma unroll
        for (int kk = 0; kk < 2; kk++) {
            uint32_t a[2][4], b[8][2];
#pragma unroll
            for (int mt = 0; mt < 2; mt++) {
                uint32_t addr = sA +
                    (uint32_t)((wm + mt * 16 + (lane & 15)) * SPITCH + kk * 16 + (lane >> 4) * 8) * 2;
                ldmat4(a[mt], addr);
            }
#pragma unroll
            for (int np = 0; np < 4; np++) {
                int brow = wn + np * 16 + (lane & 7) + ((lane & 16) ? 8 : 0);
                int bcol = kk * 16 + ((lane & 8) ? 8 : 0);
                uint32_t q[4];
                ldmat4(q, sB + (uint32_t)(brow * SPITCH + bcol) * 2);
                b[np * 2][0] = q[0]; b[np * 2][1] = q[1];
                b[np * 2 + 1][0] = q[2]; b[np * 2 + 1][1] = q[3];
            }
#pragma unroll
            for (int mt = 0; mt < 2; mt++)
#pragma unroll
                for (int nt = 0; nt < 8; nt++)
                    mma16816(acc[mt][nt], a[mt], b[nt]);
        }
    }

#pragma unroll
    for (int mt = 0; mt < 2; mt++) {
#pragma unroll
        for (int nt = 0; nt < 8; nt++) {
            int gcol = bn + wn + nt * 8 + (lane & 3) * 2;
            if (gcol >= Ntot) continue;
            float bx = bias[gcol], by = bias[gcol + 1];
            int r0 = bm + wm + mt * 16 + (lane >> 2);
            float2 v0 = make_float2(acc[mt][nt][0] + bx, acc[mt][nt][1] + by);
            float2 v1 = make_float2(acc[mt][nt][2] + bx, acc[mt][nt][3] + by);
            *(float2*)(C + (size_t)r0 * Ntot + gcol) = v0;
            *(float2*)(C + (size_t)(r0 + 8) * Ntot + gcol) = v1;
        }
    }
}

// ---------------------------------------------------------------------------
// Chain step: out[64,1024] = tanh(P_t + H@W^T); writes fp32 next-state and
// ext bf16 [hi|lo|hi] history row. grid=128, 256 threads, CTA = 8 cols x 64 rows.
// ---------------------------------------------------------------------------
__global__ void __launch_bounds__(256) chain_step_k(
    const float* __restrict__ P_t, const float* __restrict__ h_in,
    const float* __restrict__ W,
    float* __restrict__ h_out, __nv_bfloat16* __restrict__ He_t)
{
    __shared__ float Hs[64][128];    // 32KB
    __shared__ float Ws[8][132];     // padded: conflict-free

    int tid = threadIdx.x;
    int tx = tid & 7, ty = tid >> 3;   // col, row(0..31)
    int n0 = blockIdx.x * 8;

    float a00 = 0.f, a01 = 0.f, a10 = 0.f, a11 = 0.f;

    for (int kc = 0; kc < 8; kc++) {
        int k0 = kc * 128;
#pragma unroll
        for (int i = 0; i < 8; i++) {
            int idx = tid + i * 256;          // 2048 float4 total
            int r = idx >> 5, k4 = idx & 31;
            *(float4*)&Hs[r][k4 * 4] = *(const float4*)&h_in[r * NH + k0 + k4 * 4];
        }
        {
            int r = tid >> 5, k4 = tid & 31;  // 256 float4
            *(float4*)&Ws[r][k4 * 4] = *(const float4*)&W[(size_t)(n0 + r) * NH + k0 + k4 * 4];
        }
        __syncthreads();

#pragma unroll
        for (int k4 = 0; k4 < 32; k4++) {
            float4 w  = *(float4*)&Ws[tx][k4 * 4];
            float4 ha = *(float4*)&Hs[ty][k4 * 4];
            float4 hb = *(float4*)&Hs[ty + 32][k4 * 4];
            a00 = fmaf(ha.x, w.x, a00); a01 = fmaf(ha.y, w.y, a01);
            a00 = fmaf(ha.z, w.z, a00); a01 = fmaf(ha.w, w.w, a01);
            a10 = fmaf(hb.x, w.x, a10); a11 = fmaf(hb.y, w.y, a11);
            a10 = fmaf(hb.z, w.z, a10); a11 = fmaf(hb.w, w.w, a11);
        }
        __syncthreads();
    }

    int n = n0 + tx;
    float v0 = tanhf(P_t[ty * NH + n] + a00 + a01);
    float v1 = tanhf(P_t[(ty + 32) * NH + n] + a10 + a11);
    h_out[ty * NH + n]        = v0;
    h_out[(ty + 32) * NH + n] = v1;

    __nv_bfloat16 h0b = __float2bfloat16(v0);
    __nv_bfloat16 h1b = __float2bfloat16(v1);
    __nv_bfloat16 l0b = __float2bfloat16(v0 - __bfloat162float(h0b));
    __nv_bfloat16 l1b = __float2bfloat16(v1 - __bfloat162float(h1b));
    __nv_bfloat16* d0 = He_t + (size_t)ty * K3 + n;
    __nv_bfloat16* d1 = He_t + (size_t)(ty + 32) * K3 + n;
    d0[0] = h0b; d0[1024] = l0b; d0[2048] = h0b;
    d1[0] = h1b; d1[1024] = l1b; d1[2048] = h1b;
}

// ---------------------------------------------------------------------------
extern "C" void kernel_launch(void* const* d_in, const int* in_sizes, int n_in,
                              void* d_out, int out_size)
{
    const int*   inputs = (const int*)  d_in[0];
    const float* hidden = (const float*)d_in[1];
    const float* emb    = (const float*)d_in[2];
    const float* W0     = (const float*)d_in[3];
    const float* Wh0    = (const float*)d_in[4];
    const float* b0     = (const float*)d_in[5];
    const float* W1     = (const float*)d_in[6];
    const float* Wh1    = (const float*)d_in[7];
    const float* b1     = (const float*)d_in[8];
    const float* Wd     = (const float*)d_in[9];
    const float* bd     = (const float*)d_in[10];
    float* out = (float*)d_out;

    static bool inited = false;
    static float *pXp, *pYp, *ph0, *ph1;
    static __nv_bfloat16 *pXe, *pW0e, *pW1e, *pWde, *pH0e, *pH1e;
    if (!inited) {
        cudaGetSymbolAddress((void**)&pXp,  g_Xp);
        cudaGetSymbolAddress((void**)&pYp,  g_Yp);
        cudaGetSymbolAddress((void**)&ph0,  g_h0);
        cudaGetSymbolAddress((void**)&ph1,  g_h1);
        cudaGetSymbolAddress((void**)&pXe,  g_Xe);
        cudaGetSymbolAddress((void**)&pW0e, g_W0e);
        cudaGetSymbolAddress((void**)&pW1e, g_W1e);
        cudaGetSymbolAddress((void**)&pWde, g_Wde);
        cudaGetSymbolAddress((void**)&pH0e, g_H0e);
        cudaGetSymbolAddress((void**)&pH1e, g_H1e);
        cudaFuncSetAttribute(gemm_mma, cudaFuncAttributeMaxDynamicSharedMemorySize, GEMM_SMEM);
        inited = true;
    }

    init_hidden_k<<<(NB * NH + 255) / 256, 256>>>(hidden);

    splitB_k<<<(NH * NH + 255) / 256, 256>>>(W0, pW0e, NH, NH);
    splitB_k<<<(NH * NH + 255) / 256, 256>>>(W1, pW1e, NH, NH);
    splitB_k<<<(NVP * NH + 255) / 256, 256>>>(Wd, pWde, NV, NVP);
    gather_splitA_k<<<MROWS, 256>>>(emb, inputs, pXe);

    // Xp = X @ W0^T + b0
    { dim3 g(MROWS / 128, NH / 128); gemm_mma<<<g, 256, GEMM_SMEM>>>(pXe, pW0e, b0, pXp, NH); }

    // h0 chain (one matmul per step)
    for (int t = 0; t < SQ; t++) {
        int pin = t & 1, pout = 1 - pin;
        chain_step_k<<<128, 256>>>(pXp + (size_t)t * NB * NH,
                                   ph0 + (size_t)pin * NB * NH, Wh0,
                                   ph0 + (size_t)pout * NB * NH,
                                   pH0e + (size_t)t * NB * K3);
    }

    // Yp = H0 @ W1^T + b1 (batched, tensor cores)
    { dim3 g(MROWS / 128, NH / 128); gemm_mma<<<g, 256, GEMM_SMEM>>>(pH0e, pW1e, b1, pYp, NH); }

    // h1 chain
    for (int t = 0; t < SQ; t++) {
        int pin = t & 1, pout = 1 - pin;
        chain_step_k<<<128, 256>>>(pYp + (size_t)t * NB * NH,
                                   ph1 + (size_t)pin * NB * NH, Wh1,
                                   ph1 + (size_t)pout * NB * NH,
                                   pH1e + (size_t)t * NB * K3);
    }

    // logits = H1 @ Wd^T + bd
    { dim3 g(MROWS / 128, NVP / 128); gemm_mma<<<g, 256, GEMM_SMEM>>>(pH1e, pWde, bd, out, NV); }

    if ((long long)out_size >= (long long)SQ * NB * NV + 2LL * NB * NH)
        write_hidden_k<<<(NB * NH + 255) / 256, 256>>>(out + (size_t)SQ * NB * NV);
}

// round 6
// speedup vs baseline: 6.2946x; 4.9016x over previous
#include <cuda_runtime.h>
#include <cuda_fp16.h>
#include <math.h>
#include <stdint.h>

#define SQ 64
#define NB 64
#define NV 10000
#define NVP 10112            // padded to 79*128
#define NE 1024
#define NH 1024
#define MROWS (SQ*NB)        // 4096
#define KDIM 1024
#define NCH 32               // 1024/32 k-chunks
#define NSTAGE 4

// ---------------------------------------------------------------------------
// Device scratch (fp16 operands, fp32 pre-activations)
// ---------------------------------------------------------------------------
__device__ float  g_Xp[MROWS * NH];          // x@W0^T + b0
__device__ float  g_Yp[MROWS * NH];          // h0@W1^T + b1
__device__ __half g_X[MROWS * KDIM];         // gathered emb
__device__ __half g_W0h[NH * KDIM];
__device__ __half g_W1h[NH * KDIM];
__device__ __half g_Wh0h[NH * KDIM];
__device__ __half g_Wh1h[NH * KDIM];
__device__ __half g_Wdh[NVP * KDIM];
__device__ __half g_H0[MROWS * KDIM];        // h0 history (slice t = rows t*64..)
__device__ __half g_H1[MROWS * KDIM];        // h1 history
__device__ __half g_h0i[NB * KDIM];          // initial states
__device__ __half g_h1i[NB * KDIM];

// ---------------------------------------------------------------------------
// helpers
// ---------------------------------------------------------------------------
__device__ __forceinline__ uint32_t smem_u32(const void* p) {
    uint32_t a;
    asm("{ .reg .u64 t; cvta.to.shared.u64 t, %1; cvt.u32.u64 %0, t; }" : "=r"(a) : "l"(p));
    return a;
}
__device__ __forceinline__ void cpasync16(uint32_t dst, const void* src) {
    asm volatile("cp.async.cg.shared.global [%0], [%1], 16;" :: "r"(dst), "l"(src) : "memory");
}
__device__ __forceinline__ void ldmat4(uint32_t* r, uint32_t addr) {
    asm volatile("ldmatrix.sync.aligned.m8n8.x4.shared.b16 {%0,%1,%2,%3}, [%4];"
                 : "=r"(r[0]), "=r"(r[1]), "=r"(r[2]), "=r"(r[3]) : "r"(addr));
}
__device__ __forceinline__ void ldmat2(uint32_t* r, uint32_t addr) {
    asm volatile("ldmatrix.sync.aligned.m8n8.x2.shared.b16 {%0,%1}, [%2];"
                 : "=r"(r[0]), "=r"(r[1]) : "r"(addr));
}
__device__ __forceinline__ void mma16816(float* c, const uint32_t* a, const uint32_t* b) {
    asm volatile("mma.sync.aligned.m16n8k16.row.col.f32.f16.f16.f32 "
                 "{%0,%1,%2,%3}, {%4,%5,%6,%7}, {%8,%9}, {%0,%1,%2,%3};"
                 : "+f"(c[0]), "+f"(c[1]), "+f"(c[2]), "+f"(c[3])
                 : "r"(a[0]), "r"(a[1]), "r"(a[2]), "r"(a[3]), "r"(b[0]), "r"(b[1]));
}

// ---------------------------------------------------------------------------
// conversion / init kernels
// ---------------------------------------------------------------------------
__global__ void cvtW_k(const float* __restrict__ src, __half* __restrict__ dst,
                       int rows, int rowsPad) {
    int i = blockIdx.x * blockDim.x + threadIdx.x;
    if (i >= rowsPad * KDIM) return;
    int r = i >> 10;
    dst[i] = (r < rows) ? __float2half(src[i]) : __float2half(0.f);
}

__global__ void gatherX_k(const float* __restrict__ emb, const int* __restrict__ inputs,
                          __half* __restrict__ dst) {
    int row = blockIdx.x;
    const float* src = emb + (size_t)inputs[row] * NE;
    __half* d = dst + (size_t)row * KDIM;
    for (int j = threadIdx.x; j < NE; j += blockDim.x)
        d[j] = __float2half(src[j]);
}

__global__ void initH_k(const float* __restrict__ hidden) {
    int i = blockIdx.x * blockDim.x + threadIdx.x;
    if (i < NB * KDIM) {
        g_h0i[i] = __float2half(hidden[i]);
        g_h1i[i] = __float2half(hidden[NB * KDIM + i]);
    }
}

__global__ void write_hidden_k(float* __restrict__ out) {
    int i = blockIdx.x * blockDim.x + threadIdx.x;
    if (i < NB * KDIM) {
        out[i]             = __half2float(g_H0[(size_t)63 * NB * KDIM + i]);
        out[NB * KDIM + i] = __half2float(g_H1[(size_t)63 * NB * KDIM + i]);
    }
}

// ---------------------------------------------------------------------------
// fp16 mma.sync GEMM, 4-stage cp.async pipeline (structure identical to the
// verified bf16 version; dtype swapped). C = bias + A@B^T, fp32 out.
// CTA 128x128, 8 warps (32x64), K-chunk 32. grid=(32, rowsPad/128), 256 thr.
// ---------------------------------------------------------------------------
#define SPITCH 40
#define STAGE_ELEMS (2 * 128 * SPITCH)
#define GEMM_SMEM (NSTAGE * STAGE_ELEMS * 2)

__global__ void __launch_bounds__(256, 2) gemm_mma(
    const __half* __restrict__ A, const __half* __restrict__ B,
    const float* __restrict__ bias, float* __restrict__ C, int Ntot)
{
    extern __shared__ __half sm[];
    uint32_t sbase = smem_u32(sm);

    int tid  = threadIdx.x;
    int lane = tid & 31;
    int wid  = tid >> 5;
    int wm   = (wid & 3) * 32;
    int wn   = (wid >> 2) * 64;
    int bm   = blockIdx.x * 128;
    int bn   = blockIdx.y * 128;

    float acc[2][8][4];
#pragma unroll
    for (int mt = 0; mt < 2; mt++)
#pragma unroll
        for (int nt = 0; nt < 8; nt++)
#pragma unroll
            for (int j = 0; j < 4; j++) acc[mt][nt][j] = 0.f;

    int lrow[2], lseg[2];
#pragma unroll
    for (int i = 0; i < 2; i++) {
        int u = tid + i * 256;
        lrow[i] = u >> 2;
        lseg[i] = u & 3;
    }

#pragma unroll
    for (int p = 0; p < NSTAGE - 1; p++) {
        uint32_t st = sbase + p * (STAGE_ELEMS * 2);
        int koff = p * 32;
#pragma unroll
        for (int i = 0; i < 2; i++) {
            uint32_t off = (uint32_t)(lrow[i] * SPITCH + lseg[i] * 8) * 2;
            cpasync16(st + off,                    A + (size_t)(bm + lrow[i]) * KDIM + koff + lseg[i] * 8);
            cpasync16(st + 128 * SPITCH * 2 + off, B + (size_t)(bn + lrow[i]) * KDIM + koff + lseg[i] * 8);
        }
        asm volatile("cp.async.commit_group;" ::: "memory");
    }

    for (int c = 0; c < NCH; c++) {
        asm volatile("cp.async.wait_group %0;" :: "n"(NSTAGE - 2) : "memory");
        __syncthreads();

        int cn = c + NSTAGE - 1;
        if (cn < NCH) {
            uint32_t st = sbase + (cn & (NSTAGE - 1)) * (STAGE_ELEMS * 2);
            int koff = cn * 32;
#pragma unroll
            for (int i = 0; i < 2; i++) {
                uint32_t off = (uint32_t)(lrow[i] * SPITCH + lseg[i] * 8) * 2;
                cpasync16(st + off,                    A + (size_t)(bm + lrow[i]) * KDIM + koff + lseg[i] * 8);
                cpasync16(st + 128 * SPITCH * 2 + off, B + (size_t)(bn + lrow[i]) * KDIM + koff + lseg[i] * 8);
            }
        }
        asm volatile("cp.async.commit_group;" ::: "memory");

        uint32_t sA = sbase + (c & (NSTAGE - 1)) * (STAGE_ELEMS * 2);
        uint32_t sB = sA + 128 * SPITCH * 2;
#pragma unroll
        for (int kk = 0; kk < 2; kk++) {
            uint32_t a[2][4], b[8][2];
#pragma unroll
            for (int mt = 0; mt < 2; mt++) {
                uint32_t addr = sA +
                    (uint32_t)((wm + mt * 16 + (lane & 15)) * SPITCH + kk * 16 + (lane >> 4) * 8) * 2;
                ldmat4(a[mt], addr);
            }
#pragma unroll
            for (int np = 0; np < 4; np++) {
                int brow = wn + np * 16 + (lane & 7) + ((lane & 16) ? 8 : 0);
                int bcol = kk * 16 + ((lane & 8) ? 8 : 0);
                uint32_t q[4];
                ldmat4(q, sB + (uint32_t)(brow * SPITCH + bcol) * 2);
                b[np * 2][0] = q[0]; b[np * 2][1] = q[1];
                b[np * 2 + 1][0] = q[2]; b[np * 2 + 1][1] = q[3];
            }
#pragma unroll
            for (int mt = 0; mt < 2; mt++)
#pragma unroll
                for (int nt = 0; nt < 8; nt++)
                    mma16816(acc[mt][nt], a[mt], b[nt]);
        }
    }

#pragma unroll
    for (int mt = 0; mt < 2; mt++) {
#pragma unroll
        for (int nt = 0; nt < 8; nt++) {
            int gcol = bn + wn + nt * 8 + (lane & 3) * 2;
            if (gcol >= Ntot) continue;
            float bx = bias[gcol], by = bias[gcol + 1];
            int r0 = bm + wm + mt * 16 + (lane >> 2);
            float2 v0 = make_float2(acc[mt][nt][0] + bx, acc[mt][nt][1] + by);
            float2 v1 = make_float2(acc[mt][nt][2] + bx, acc[mt][nt][3] + by);
            *(float2*)(C + (size_t)r0 * Ntot + gcol) = v0;
            *(float2*)(C + (size_t)(r0 + 8) * Ntot + gcol) = v1;
        }
    }
}

// ---------------------------------------------------------------------------
// Tensor-core chain step: Hout[64,1024] = tanh(P_t + hprev @ W^T), fp16 out.
// grid = 128 CTAs (8 N-cols each), 128 threads (4 warps = 4 m16 slabs).
// K loop: 8 chunks of 128, 2-stage cp.async double buffer.
// ---------------------------------------------------------------------------
#define CPITCH 136    // halves per smem row (272B, 16B-aligned, conflict-free)

__global__ void __launch_bounds__(128) chain_step_k(
    const float* __restrict__ P_t, const __half* __restrict__ hprev,
    const __half* __restrict__ W, __half* __restrict__ Hout)
{
    __shared__ __half hs[2][64 * CPITCH];
    __shared__ __half ws[2][8 * CPITCH];

    int tid  = threadIdx.x;
    int lane = tid & 31;
    int wid  = tid >> 5;
    int m0   = wid * 16;
    int n0   = blockIdx.x * 8;

    uint32_t hsb[2] = { smem_u32(hs[0]), smem_u32(hs[1]) };
    uint32_t wsb[2] = { smem_u32(ws[0]), smem_u32(ws[1]) };

    float acc[4] = {0.f, 0.f, 0.f, 0.f};

    // load chunk 0 into stage 0
    {
#pragma unroll
        for (int i = 0; i < 8; i++) {
            int u = tid + i * 128;          // 1024 16B-units of h
            int r = u >> 4, seg = u & 15;
            cpasync16(hsb[0] + (uint32_t)(r * CPITCH + seg * 8) * 2,
                      hprev + (size_t)r * KDIM + seg * 8);
        }
        { int r = tid >> 4, seg = tid & 15;   // 128 units of W
          cpasync16(wsb[0] + (uint32_t)(r * CPITCH + seg * 8) * 2,
                    W + (size_t)(n0 + r) * KDIM + seg * 8); }
        asm volatile("cp.async.commit_group;" ::: "memory");
    }

    for (int c = 0; c < 8; c++) {
        int s = c & 1;
        if (c + 1 < 8) {
            int k0 = (c + 1) * 128;
#pragma unroll
            for (int i = 0; i < 8; i++) {
                int u = tid + i * 128;
                int r = u >> 4, seg = u & 15;
                cpasync16(hsb[s ^ 1] + (uint32_t)(r * CPITCH + seg * 8) * 2,
                          hprev + (size_t)r * KDIM + k0 + seg * 8);
            }
            { int r = tid >> 4, seg = tid & 15;
              cpasync16(wsb[s ^ 1] + (uint32_t)(r * CPITCH + seg * 8) * 2,
                        W + (size_t)(n0 + r) * KDIM + k0 + seg * 8); }
            asm volatile("cp.async.commit_group;" ::: "memory");
            asm volatile("cp.async.wait_group 1;" ::: "memory");
        } else {
            asm volatile("cp.async.wait_group 0;" ::: "memory");
        }
        __syncthreads();

#pragma unroll
        for (int kk = 0; kk < 8; kk++) {
            uint32_t a[4], b[2];
            ldmat4(a, hsb[s] + (uint32_t)((m0 + (lane & 15)) * CPITCH + kk * 16 + (lane >> 4) * 8) * 2);
            ldmat2(b, wsb[s] + (uint32_t)((lane & 7) * CPITCH + kk * 16 + ((lane >> 3) & 1) * 8) * 2);
            mma16816(acc, a, b);
        }
        __syncthreads();
    }

    int r0 = m0 + (lane >> 2);
    int c0 = n0 + (lane & 3) * 2;
    float v0 = tanhf(P_t[r0 * NH + c0]           + acc[0]);
    float v1 = tanhf(P_t[r0 * NH + c0 + 1]       + acc[1]);
    float v2 = tanhf(P_t[(r0 + 8) * NH + c0]     + acc[2]);
    float v3 = tanhf(P_t[(r0 + 8) * NH + c0 + 1] + acc[3]);
    Hout[r0 * KDIM + c0]           = __float2half(v0);
    Hout[r0 * KDIM + c0 + 1]       = __float2half(v1);
    Hout[(r0 + 8) * KDIM + c0]     = __float2half(v2);
    Hout[(r0 + 8) * KDIM + c0 + 1] = __float2half(v3);
}

// ---------------------------------------------------------------------------
extern "C" void kernel_launch(void* const* d_in, const int* in_sizes, int n_in,
                              void* d_out, int out_size)
{
    const int*   inputs = (const int*)  d_in[0];
    const float* hidden = (const float*)d_in[1];
    const float* emb    = (const float*)d_in[2];
    const float* W0     = (const float*)d_in[3];
    const float* Wh0    = (const float*)d_in[4];
    const float* b0     = (const float*)d_in[5];
    const float* W1     = (const float*)d_in[6];
    const float* Wh1    = (const float*)d_in[7];
    const float* b1     = (const float*)d_in[8];
    const float* Wd     = (const float*)d_in[9];
    const float* bd     = (const float*)d_in[10];
    float* out = (float*)d_out;

    static bool inited = false;
    static float *pXp, *pYp;
    static __half *pX, *pW0h, *pW1h, *pWh0h, *pWh1h, *pWdh, *pH0, *pH1, *ph0i, *ph1i;
    if (!inited) {
        cudaGetSymbolAddress((void**)&pXp,   g_Xp);
        cudaGetSymbolAddress((void**)&pYp,   g_Yp);
        cudaGetSymbolAddress((void**)&pX,    g_X);
        cudaGetSymbolAddress((void**)&pW0h,  g_W0h);
        cudaGetSymbolAddress((void**)&pW1h,  g_W1h);
        cudaGetSymbolAddress((void**)&pWh0h, g_Wh0h);
        cudaGetSymbolAddress((void**)&pWh1h, g_Wh1h);
        cudaGetSymbolAddress((void**)&pWdh,  g_Wdh);
        cudaGetSymbolAddress((void**)&pH0,   g_H0);
        cudaGetSymbolAddress((void**)&pH1,   g_H1);
        cudaGetSymbolAddress((void**)&ph0i,  g_h0i);
        cudaGetSymbolAddress((void**)&ph1i,  g_h1i);
        cudaFuncSetAttribute(gemm_mma, cudaFuncAttributeMaxDynamicSharedMemorySize, GEMM_SMEM);
        inited = true;
    }

    initH_k<<<(NB * KDIM + 255) / 256, 256>>>(hidden);

    cvtW_k<<<(NH * KDIM + 255) / 256, 256>>>(W0,  pW0h,  NH, NH);
    cvtW_k<<<(NH * KDIM + 255) / 256, 256>>>(W1,  pW1h,  NH, NH);
    cvtW_k<<<(NH * KDIM + 255) / 256, 256>>>(Wh0, pWh0h, NH, NH);
    cvtW_k<<<(NH * KDIM + 255) / 256, 256>>>(Wh1, pWh1h, NH, NH);
    cvtW_k<<<(NVP * KDIM + 255) / 256, 256>>>(Wd, pWdh, NV, NVP);
    gatherX_k<<<MROWS, 256>>>(emb, inputs, pX);

    // Xp = X @ W0^T + b0
    { dim3 g(MROWS / 128, NH / 128); gemm_mma<<<g, 256, GEMM_SMEM>>>(pX, pW0h, b0, pXp, NH); }

    // h0 chain
    for (int t = 0; t < SQ; t++) {
        const __half* prev = (t == 0) ? ph0i : pH0 + (size_t)(t - 1) * NB * KDIM;
        chain_step_k<<<128, 128>>>(pXp + (size_t)t * NB * NH, prev, pWh0h,
                                   pH0 + (size_t)t * NB * KDIM);
    }

    // Yp = H0 @ W1^T + b1
    { dim3 g(MROWS / 128, NH / 128); gemm_mma<<<g, 256, GEMM_SMEM>>>(pH0, pW1h, b1, pYp, NH); }

    // h1 chain
    for (int t = 0; t < SQ; t++) {
        const __half* prev = (t == 0) ? ph1i : pH1 + (size_t)(t - 1) * NB * KDIM;
        chain_step_k<<<128, 128>>>(pYp + (size_t)t * NB * NH, prev, pWh1h,
                                   pH1 + (size_t)t * NB * KDIM);
    }

    // logits = H1 @ Wd^T + bd
    { dim3 g(MROWS / 128, NVP / 128); gemm_mma<<<g, 256, GEMM_SMEM>>>(pH1, pWdh, bd, out, NV); }

    if ((long long)out_size >= (long long)SQ * NB * NV + 2LL * NB * KDIM)
        write_hidden_k<<<(NB * KDIM + 255) / 256, 256>>>(out + (size_t)SQ * NB * NV);
}